// round 9
// baseline (speedup 1.0000x reference)
#include <cuda_runtime.h>
#include <math.h>

#define BANDS 64
#define CHA   64
#define NPIX  16384
#define RRANK 3
#define ITEN  20

#define PB_CTAS 32          // CTAs per band
#define SUBT    4           // subtiles per CTA
#define TP      128         // pixels per subtile
#define PIX_PER_CTA (SUBT*TP)   // 512
#define NTHREADS 256
#define MAXSWEEP 10
#define TSTR 68             // tile row stride in floats (272B, 16B-aligned)
#define NPART (PB_CTAS*4)   // 128 gram partials per band (4 pixel-groups/CTA)

// ---- device scratch (static module memory; no runtime allocation) ----
__device__ float  g_Gpart[(size_t)BANDS*NPART*CHA*CHA];        // 134 MB
__device__ float  g_Ur2[2][BANDS*CHA*RRANK];                   // ping-pong Ur
__device__ float  g_V[(size_t)BANDS*CHA*CHA];                  // warm-start V
__device__ float  g_T[(size_t)BANDS*CHA*CHA];                  // matmul temp
__device__ float  g_c[(size_t)BANDS*RRANK*NPIX];               // rank-3 state (12.6 MB)
__device__ float  g_losspart[2][ITEN][BANDS*PB_CTAS];
__device__ double g_dpart[1024];
__device__ float  g_rho0;

// packed f32x2 fused-multiply-add (sm_100+ PTX; ptxas never auto-fuses)
#define FMA2(acc,aa,bb) asm("fma.rn.f32x2 %0, %1, %2, %3;" : "=l"(acc) : "l"(aa), "l"(bb), "l"(acc))
#define PACK2(dst,lo,hi) asm("mov.b64 %0,{%1,%2};" : "=l"(dst) : "f"(lo), "f"(hi))
#define PACKD(dst,v)     asm("mov.b64 %0,{%1,%1};" : "=l"(dst) : "f"(v))
#define UNPK2(lo,hi,src) asm("mov.b64 {%0,%1}, %2;" : "=f"(lo), "=f"(hi) : "l"(src))

// ============================================================
// rho0 = 0.5 * mean(W)  (deterministic, double accumulation)
// ============================================================
__global__ __launch_bounds__(NTHREADS) void k_wsum1(const float* __restrict__ W)
{
    __shared__ double rd[NTHREADS];
    const size_t base = (size_t)blockIdx.x * 65536;
    double s = 0.0;
    for (int i = threadIdx.x; i < 65536; i += NTHREADS) s += (double)W[base + i];
    rd[threadIdx.x] = s;
    __syncthreads();
    for (int st = NTHREADS/2; st > 0; st >>= 1) {
        if (threadIdx.x < st) rd[threadIdx.x] += rd[threadIdx.x + st];
        __syncthreads();
    }
    if (threadIdx.x == 0) g_dpart[blockIdx.x] = rd[0];
}

__global__ __launch_bounds__(NTHREADS) void k_wsum2()
{
    __shared__ double rd[NTHREADS];
    double s = 0.0;
    for (int i = threadIdx.x; i < 1024; i += NTHREADS) s += g_dpart[i];
    rd[threadIdx.x] = s;
    __syncthreads();
    for (int st = NTHREADS/2; st > 0; st >>= 1) {
        if (threadIdx.x < st) rd[threadIdx.x] += rd[threadIdx.x + st];
        __syncthreads();
    }
    if (threadIdx.x == 0) g_rho0 = (float)(0.5 * rd[0] / 67108864.0);
}

// ============================================================
// init V = I per band (warm-start seed)
// ============================================================
__global__ __launch_bounds__(NTHREADS) void k_initV()
{
    const int b = blockIdx.x;
    for (int e = threadIdx.x; e < CHA * CHA; e += NTHREADS)
        g_V[(size_t)b * (CHA * CHA) + e] = ((e >> 6) == (e & 63)) ? 1.0f : 0.0f;
}

// ============================================================
// shared 8x8-blocked gram over the smem tile (one pixel group)
//   gg: pixel group 0..3, thread covers rows tr..tr+7 x cols tc..tc+7
// ============================================================
__device__ __forceinline__ void gram8x8(const float* __restrict__ tile,
                                        int gg, int tr, int tc,
                                        unsigned long long acc[32])
{
    const int p0 = gg * 32;
#pragma unroll 2
    for (int pp = p0; pp < p0 + 32; ++pp) {
        const float4 a0 = *(const float4*)&tile[pp * TSTR + tr];
        const float4 a1 = *(const float4*)&tile[pp * TSTR + tr + 4];
        const float4 b0 = *(const float4*)&tile[pp * TSTR + tc];
        const float4 b1 = *(const float4*)&tile[pp * TSTR + tc + 4];
        unsigned long long B0, B1, B2, B3, A;
        PACK2(B0, b0.x, b0.y); PACK2(B1, b0.z, b0.w);
        PACK2(B2, b1.x, b1.y); PACK2(B3, b1.z, b1.w);
        PACKD(A, a0.x); FMA2(acc[0],  A, B0); FMA2(acc[1],  A, B1); FMA2(acc[2],  A, B2); FMA2(acc[3],  A, B3);
        PACKD(A, a0.y); FMA2(acc[4],  A, B0); FMA2(acc[5],  A, B1); FMA2(acc[6],  A, B2); FMA2(acc[7],  A, B3);
        PACKD(A, a0.z); FMA2(acc[8],  A, B0); FMA2(acc[9],  A, B1); FMA2(acc[10], A, B2); FMA2(acc[11], A, B3);
        PACKD(A, a0.w); FMA2(acc[12], A, B0); FMA2(acc[13], A, B1); FMA2(acc[14], A, B2); FMA2(acc[15], A, B3);
        PACKD(A, a1.x); FMA2(acc[16], A, B0); FMA2(acc[17], A, B1); FMA2(acc[18], A, B2); FMA2(acc[19], A, B3);
        PACKD(A, a1.y); FMA2(acc[20], A, B0); FMA2(acc[21], A, B1); FMA2(acc[22], A, B2); FMA2(acc[23], A, B3);
        PACKD(A, a1.z); FMA2(acc[24], A, B0); FMA2(acc[25], A, B1); FMA2(acc[26], A, B2); FMA2(acc[27], A, B3);
        PACKD(A, a1.w); FMA2(acc[28], A, B0); FMA2(acc[29], A, B1); FMA2(acc[30], A, B2); FMA2(acc[31], A, B3);
    }
}

__device__ __forceinline__ void gram_store(unsigned long long acc[32],
                                           int b, int cta, int gg, int tr, int tc)
{
    const size_t gb = (((size_t)(b * PB_CTAS + cta)) * 4 + gg) * (CHA * CHA);
#pragma unroll
    for (int i = 0; i < 8; ++i) {
#pragma unroll
        for (int j = 0; j < 4; ++j) {
            float lo, hi;
            UNPK2(lo, hi, acc[i * 4 + j]);
            g_Gpart[gb + (size_t)(tr + i) * CHA + tc + j * 2    ] = lo;
            g_Gpart[gb + (size_t)(tr + i) * CHA + tc + j * 2 + 1] = hi;
        }
    }
}

// ============================================================
// Gram of initial L (= x)
// ============================================================
__global__ __launch_bounds__(NTHREADS, 2) void k_gram0(const float* __restrict__ x)
{
    __shared__ __align__(16) float tile[TP * TSTR];
    const int tid = threadIdx.x;
    const int cta = blockIdx.x;
    const int b   = blockIdx.y;
    const int p   = tid & 127;
    const int cg  = tid >> 7;
    const int gg  = tid >> 6;
    const int id  = tid & 63;
    const int tr  = (id >> 3) << 3;
    const int tc  = (id & 7) << 3;

    unsigned long long acc[32];
    { float z = 0.0f;
#pragma unroll
      for (int i = 0; i < 32; ++i) PACKD(acc[i], z); }

    for (int s = 0; s < SUBT; ++s) {
        const int n = cta * PIX_PER_CTA + s * TP + p;
        const size_t cbase = (((size_t)b * CHA + cg * 32) << 14) + n;
        __syncthreads();
#pragma unroll
        for (int q = 0; q < 8; ++q) {
            const size_t i0 = cbase + ((size_t)(q * 4) << 14);
            float4 v;
            v.x = x[i0];
            v.y = x[i0 + (size_t)(1 << 14)];
            v.z = x[i0 + (size_t)(2 << 14)];
            v.w = x[i0 + (size_t)(3 << 14)];
            *(float4*)&tile[p * TSTR + cg * 32 + q * 4] = v;
        }
        __syncthreads();
        gram8x8(tile, gg, tr, tc, acc);
    }
    gram_store(acc, b, cta, gg, tr, tc);
}

// ============================================================
// Eigen kernel: reduce G partials, warm-start pre-rotation,
// parallel Jacobi with R6's proven full-off-diagonal convergence,
// write Ur + V
// ============================================================
__device__ __forceinline__ int rrperm(int k, int r)
{
    return (k == 0) ? 0 : 1 + ((k - 1 + r) % 63);
}

__global__ __launch_bounds__(NTHREADS) void k_eigen(int t)
{
    __shared__ float As[64 * 65];
    __shared__ float Vs[64 * 65];
    __shared__ float cs_c[32], cs_s[32];
    __shared__ int   ppv[32], qqv[32];
    __shared__ float red[NTHREADS];
    __shared__ float soff, sdg;
    __shared__ int   sflag;
    __shared__ int   topi[RRANK];

    const int tid = threadIdx.x;
    const int b   = blockIdx.x;
    const int tr  = (tid >> 4) << 2;
    const int tc  = (tid & 15) << 2;

    // reduce partial Grams (fixed order, vectorized)
    {
        const size_t base = (size_t)b * NPART * (CHA * CHA) + (size_t)tid * 16;
        float4 s0 = make_float4(0,0,0,0), s1 = s0, s2 = s0, s3 = s0;
        for (int pp = 0; pp < NPART; ++pp) {
            const float4* gp = (const float4*)&g_Gpart[base + (size_t)pp * (CHA * CHA)];
            float4 v0 = gp[0], v1 = gp[1], v2 = gp[2], v3 = gp[3];
            s0.x += v0.x; s0.y += v0.y; s0.z += v0.z; s0.w += v0.w;
            s1.x += v1.x; s1.y += v1.y; s1.z += v1.z; s1.w += v1.w;
            s2.x += v2.x; s2.y += v2.y; s2.z += v2.z; s2.w += v2.w;
            s3.x += v3.x; s3.y += v3.y; s3.z += v3.z; s3.w += v3.w;
        }
        const int e0 = tid * 16;
        float vals[16] = {s0.x,s0.y,s0.z,s0.w, s1.x,s1.y,s1.z,s1.w,
                          s2.x,s2.y,s2.z,s2.w, s3.x,s3.y,s3.z,s3.w};
#pragma unroll
        for (int k = 0; k < 16; ++k) {
            int e = e0 + k;
            As[(e >> 6) * 65 + (e & 63)] = vals[k];
        }
    }
    // load previous V (identity at t=0)
    for (int e = tid; e < CHA * CHA; e += NTHREADS)
        Vs[(e >> 6) * 65 + (e & 63)] = g_V[(size_t)b * (CHA * CHA) + e];
    __syncthreads();

    // warm-start pre-rotation: A <- V^T A V  (temp via global scratch)
    if (t > 0) {
        float* gT = g_T + (size_t)b * (CHA * CHA);
        float tt[16];
#pragma unroll
        for (int i = 0; i < 16; ++i) tt[i] = 0.0f;
        for (int k = 0; k < 64; ++k) {
            float a0 = As[(tr  ) * 65 + k], a1 = As[(tr+1) * 65 + k];
            float a2 = As[(tr+2) * 65 + k], a3 = As[(tr+3) * 65 + k];
            float v0 = Vs[k * 65 + tc], v1 = Vs[k * 65 + tc + 1];
            float v2 = Vs[k * 65 + tc + 2], v3 = Vs[k * 65 + tc + 3];
            tt[0]  += a0*v0; tt[1]  += a0*v1; tt[2]  += a0*v2; tt[3]  += a0*v3;
            tt[4]  += a1*v0; tt[5]  += a1*v1; tt[6]  += a1*v2; tt[7]  += a1*v3;
            tt[8]  += a2*v0; tt[9]  += a2*v1; tt[10] += a2*v2; tt[11] += a2*v3;
            tt[12] += a3*v0; tt[13] += a3*v1; tt[14] += a3*v2; tt[15] += a3*v3;
        }
#pragma unroll
        for (int i = 0; i < 4; ++i)
#pragma unroll
            for (int j = 0; j < 4; ++j)
                gT[(tr + i) * 64 + tc + j] = tt[i * 4 + j];
        __syncthreads();
#pragma unroll
        for (int i = 0; i < 16; ++i) tt[i] = 0.0f;
        for (int k = 0; k < 64; ++k) {
            float a0 = Vs[k * 65 + tr], a1 = Vs[k * 65 + tr + 1];
            float a2 = Vs[k * 65 + tr + 2], a3 = Vs[k * 65 + tr + 3];
            float v0 = gT[k * 64 + tc], v1 = gT[k * 64 + tc + 1];
            float v2 = gT[k * 64 + tc + 2], v3 = gT[k * 64 + tc + 3];
            tt[0]  += a0*v0; tt[1]  += a0*v1; tt[2]  += a0*v2; tt[3]  += a0*v3;
            tt[4]  += a1*v0; tt[5]  += a1*v1; tt[6]  += a1*v2; tt[7]  += a1*v3;
            tt[8]  += a2*v0; tt[9]  += a2*v1; tt[10] += a2*v2; tt[11] += a2*v3;
            tt[12] += a3*v0; tt[13] += a3*v1; tt[14] += a3*v2; tt[15] += a3*v3;
        }
        __syncthreads();
#pragma unroll
        for (int i = 0; i < 4; ++i)
#pragma unroll
            for (int j = 0; j < 4; ++j)
                As[(tr + i) * 65 + tc + j] = tt[i * 4 + j];
        __syncthreads();
    }

    for (int sw = 0; sw < MAXSWEEP; ++sw) {
        // convergence check BEFORE the sweep (warm starts exit immediately)
        float off = 0.0f, dg = 0.0f;
        for (int e = tid; e < 4096; e += NTHREADS) {
            int rr = e >> 6, cc = e & 63;
            float v = As[rr * 65 + cc];
            if (rr == cc) dg += v * v; else off += v * v;
        }
        red[tid] = off; __syncthreads();
        for (int st = NTHREADS/2; st > 0; st >>= 1) {
            if (tid < st) red[tid] += red[tid + st];
            __syncthreads();
        }
        if (tid == 0) soff = red[0];
        __syncthreads();
        red[tid] = dg; __syncthreads();
        for (int st = NTHREADS/2; st > 0; st >>= 1) {
            if (tid < st) red[tid] += red[tid + st];
            __syncthreads();
        }
        if (tid == 0) { sdg = red[0]; sflag = (soff < 1e-11f * sdg) ? 1 : 0; }
        __syncthreads();
        if (sflag) break;

        for (int r = 0; r < 63; ++r) {
            if (tid < 32) {
                int a  = rrperm(tid, r);
                int b2 = rrperm(63 - tid, r);
                int p = a < b2 ? a : b2;
                int q = a < b2 ? b2 : a;
                ppv[tid] = p; qqv[tid] = q;
                float apq = As[p * 65 + q];
                float cc = 1.0f, ss = 0.0f;
                if (fabsf(apq) > 1e-30f) {
                    float tau = (As[q * 65 + q] - As[p * 65 + p]) / (2.0f * apq);
                    float tt  = 1.0f / (fabsf(tau) + sqrtf(1.0f + tau * tau));
                    if (tau < 0.0f) tt = -tt;
                    cc = 1.0f / sqrtf(1.0f + tt * tt);
                    ss = tt * cc;
                }
                cs_c[tid] = cc; cs_s[tid] = ss;
            }
            __syncthreads();
            // column updates on A and V  (B = A*J, V = V*J)
            for (int task = tid; task < 4096; task += NTHREADS) {
                int pi  = task >> 7;
                int rem = task & 127;
                int row = rem & 63;
                int p = ppv[pi], q = qqv[pi];
                float c = cs_c[pi], s = cs_s[pi];
                if (rem < 64) {
                    float ap = As[row * 65 + p], aq = As[row * 65 + q];
                    As[row * 65 + p] = c * ap - s * aq;
                    As[row * 65 + q] = s * ap + c * aq;
                } else {
                    float vp = Vs[row * 65 + p], vq = Vs[row * 65 + q];
                    Vs[row * 65 + p] = c * vp - s * vq;
                    Vs[row * 65 + q] = s * vp + c * vq;
                }
            }
            __syncthreads();
            // row updates on A  (A = J^T * B)
            for (int task = tid; task < 2048; task += NTHREADS) {
                int pi  = task >> 6;
                int col = task & 63;
                int p = ppv[pi], q = qqv[pi];
                float c = cs_c[pi], s = cs_s[pi];
                float ap = As[p * 65 + col], aq = As[q * 65 + col];
                As[p * 65 + col] = c * ap - s * aq;
                As[q * 65 + col] = s * ap + c * aq;
            }
            __syncthreads();
        }
    }

    // top-3 selection (descending)
    if (tid == 0) {
        int t0 = -1, t1 = -1, t2 = -1;
        for (int j = 0; j < RRANK; ++j) {
            float best = -3.4e38f; int bi = -1;
            for (int c = 0; c < 64; ++c) {
                if (c == t0 || c == t1 || c == t2) continue;
                float v = As[c * 65 + c];
                if (v > best) { best = v; bi = c; }
            }
            if (j == 0) t0 = bi; else if (j == 1) t1 = bi; else t2 = bi;
            topi[j] = bi;
        }
    }
    __syncthreads();
    // persist V for warm start, write Ur (ping-pong)
    for (int e = tid; e < CHA * CHA; e += NTHREADS)
        g_V[(size_t)b * (CHA * CHA) + e] = Vs[(e >> 6) * 65 + (e & 63)];
    if (tid < CHA * RRANK) {
        int c = tid / RRANK, j = tid % RRANK;
        g_Ur2[t & 1][b * (CHA * RRANK) + tid] = Vs[c * 65 + topi[j]];
    }
}

// ============================================================
// Fused per-iteration pass (rank-3 state, no stored L):
//   reconstruct L_t from (x, W, c_{t-1}, Ur_{t-1})  [t=0: L=x]
//   c_t = Ur_t^T L_t  -> UV_t, losses
//   L_{t+1} -> smem tile -> fused 8x8 Gram  (skipped on final)
//   store c_t  (final: write UV to out)
// ============================================================
__global__ __launch_bounds__(NTHREADS, 2) void k_iter(const float* __restrict__ x,
                                                      const float* __restrict__ W,
                                                      float* __restrict__ out,
                                                      int t, int final, int useX)
{
    __shared__ __align__(16) float tile[TP * TSTR];   // 34816 B
    __shared__ float urc[CHA * RRANK];
    __shared__ float urp[CHA * RRANK];
    __shared__ float pc[3 * NTHREADS];
    __shared__ float red[NTHREADS];

    const int tid = threadIdx.x;
    const int cta = blockIdx.x;
    const int b   = blockIdx.y;
    const int p   = tid & 127;
    const int cg  = tid >> 7;          // channel half: 0 or 1
    const int gg  = tid >> 6;          // gram pixel group 0..3
    const int id  = tid & 63;
    const int tr  = (id >> 3) << 3;
    const int tc  = (id & 7) << 3;

    if (tid < CHA * RRANK) {
        urc[tid] = g_Ur2[t & 1][b * (CHA * RRANK) + tid];
        urp[tid] = useX ? 0.0f : g_Ur2[(t - 1) & 1][b * (CHA * RRANK) + tid];
    }
    __syncthreads();   // *** R8 BUG FIX: all threads must see urc/urp before phase A ***

    const float rho_t = g_rho0 * powf(1.05f, (float)t);
    const float rho_p = useX ? 0.0f : g_rho0 * powf(1.05f, (float)(t - 1));

    unsigned long long acc[32];
    { float z = 0.0f;
#pragma unroll
      for (int i = 0; i < 32; ++i) PACKD(acc[i], z); }
    float lF = 0.0f, lU = 0.0f;

    const size_t cb = ((size_t)b * RRANK) << 14;

    for (int s = 0; s < SUBT; ++s) {
        const int n = cta * PIX_PER_CTA + s * TP + p;
        const size_t cbase = (((size_t)b * CHA + cg * 32) << 14) + n;

        // c_{t-1} for this pixel
        float cp0 = 0.0f, cp1 = 0.0f, cp2 = 0.0f;
        if (!useX) {
            cp0 = g_c[cb + n];
            cp1 = g_c[cb + NPIX + n];
            cp2 = g_c[cb + 2 * NPIX + n];
        }

        // ---- phase A: reconstruct L_t per channel, accumulate c_t partials ----
        float a0 = 0.0f, a1 = 0.0f, a2 = 0.0f;
#pragma unroll
        for (int q = 0; q < 32; ++q) {
            const int cc = cg * 32 + q;
            const size_t idx = cbase + ((size_t)q << 14);
            float xv = x[idx];
            float l;
            if (useX) {
                l = xv;
            } else {
                float wv  = W[idx];
                float uvp = urp[cc*3] * cp0 + urp[cc*3+1] * cp1 + urp[cc*3+2] * cp2;
                float mup = rho_p / (wv + rho_p);
                l = xv + mup * (uvp - xv);
            }
            a0 += urc[cc*3  ] * l;
            a1 += urc[cc*3+1] * l;
            a2 += urc[cc*3+2] * l;
        }

        __syncthreads();   // guards pc reuse AND tile (gram readers of prev subtile)
        pc[tid] = a0; pc[NTHREADS + tid] = a1; pc[2 * NTHREADS + tid] = a2;
        __syncthreads();
        const float C0 = pc[p] + pc[128 + p];
        const float C1 = pc[NTHREADS + p] + pc[NTHREADS + 128 + p];
        const float C2 = pc[2*NTHREADS + p] + pc[2*NTHREADS + 128 + p];

        // store c_t (one writer per pixel); safe: same-pixel read happened above
        if (!final && cg == 0) {
            g_c[cb + n]            = C0;
            g_c[cb + NPIX + n]     = C1;
            g_c[cb + 2 * NPIX + n] = C2;
        }

        // ---- phase B: UV, losses, L_{t+1} -> tile ----
#pragma unroll
        for (int q = 0; q < 8; ++q) {
            const int c0 = cg * 32 + q * 4;
            const size_t i0 = cbase + ((size_t)(q * 4) << 14);
            float lnv[4];
#pragma unroll
            for (int j = 0; j < 4; ++j) {
                const int cc = c0 + j;
                const size_t idx = i0 + ((size_t)j << 14);
                float uv = urc[cc*3] * C0 + urc[cc*3+1] * C1 + urc[cc*3+2] * C2;
                float xv = x[idx];
                float wv = W[idx];
                float d  = uv - xv;
                lF += wv * d * d;
                lU += uv * uv;
                if (final) {
                    out[idx] = uv;
                } else {
                    float mu = rho_t / (wv + rho_t);
                    lnv[j] = xv + mu * (uv - xv);
                }
            }
            if (!final)
                *(float4*)&tile[p * TSTR + c0] = *(float4*)lnv;
        }

        if (!final) {
            __syncthreads();
            gram8x8(tile, gg, tr, tc, acc);
        }
    }

    if (!final) gram_store(acc, b, cta, gg, tr, tc);

    // deterministic loss partials
    __syncthreads();
    red[tid] = lF; __syncthreads();
    for (int st = NTHREADS/2; st > 0; st >>= 1) {
        if (tid < st) red[tid] += red[tid + st];
        __syncthreads();
    }
    if (tid == 0) g_losspart[0][t][b * PB_CTAS + cta] = red[0];
    __syncthreads();
    red[tid] = lU; __syncthreads();
    for (int st = NTHREADS/2; st > 0; st >>= 1) {
        if (tid < st) red[tid] += red[tid + st];
        __syncthreads();
    }
    if (tid == 0) g_losspart[1][t][b * PB_CTAS + cta] = red[0];
}

// ============================================================
// final loss reduction -> out tail
// ============================================================
__global__ __launch_bounds__(NTHREADS) void k_loss_final(float* __restrict__ out)
{
    __shared__ double rd[NTHREADS];
    const int id   = blockIdx.x;       // 0..39
    const int type = id / ITEN;        // 0 = loss_F, 1 = loss
    const int t    = id % ITEN;
    double s = 0.0;
    for (int i = threadIdx.x; i < BANDS * PB_CTAS; i += NTHREADS)
        s += (double)g_losspart[type][t][i];
    rd[threadIdx.x] = s;
    __syncthreads();
    for (int st = NTHREADS/2; st > 0; st >>= 1) {
        if (threadIdx.x < st) rd[threadIdx.x] += rd[threadIdx.x + st];
        __syncthreads();
    }
    if (threadIdx.x == 0)
        out[(size_t)67108864 + (size_t)type * ITEN + t] = (float)(rd[0] / 67108864.0);
}

// ============================================================
extern "C" void kernel_launch(void* const* d_in, const int* in_sizes, int n_in,
                              void* d_out, int out_size)
{
    const float* x = (const float*)d_in[0];
    const float* W = (const float*)d_in[1];
    float* out = (float*)d_out;

    k_wsum1<<<1024, NTHREADS>>>(W);                     // launch 0
    k_wsum2<<<1, NTHREADS>>>();                         // launch 1
    k_initV<<<BANDS, NTHREADS>>>();                     // launch 2
    k_gram0<<<dim3(PB_CTAS, BANDS), NTHREADS>>>(x);     // launch 3

    for (int t = 0; t < ITEN; ++t) {
        k_eigen<<<BANDS, NTHREADS>>>(t);                // launch 4, 6, ...
        k_iter<<<dim3(PB_CTAS, BANDS), NTHREADS>>>(     // launch 5 (ncu -s 5 lands here)
            x, W, out, t, (t == ITEN - 1) ? 1 : 0, (t == 0) ? 1 : 0);
    }
    k_loss_final<<<40, NTHREADS>>>(out);
}

// round 10
// speedup vs baseline: 1.1752x; 1.1752x over previous
#include <cuda_runtime.h>
#include <math.h>

#define BANDS 64
#define CHA   64
#define NPIX  16384
#define RRANK 3
#define ITEN  20

#define PB_CTAS 32          // CTAs per band
#define SUBT    4           // subtiles per CTA
#define TP      128         // pixels per subtile
#define PIX_PER_CTA (SUBT*TP)   // 512
#define NTHREADS 256
#define MAXSWEEP 10
#define TSTR 68             // tile row stride in floats (272B, 16B-aligned)
#define NPART (PB_CTAS*2)   // 64 gram partials per band (2 pixel-groups/CTA)

// ---- device scratch (static module memory; no runtime allocation) ----
__device__ float  g_L[(size_t)BANDS*CHA*NPIX];                 // 256 MB
__device__ float  g_Gpart[(size_t)BANDS*NPART*CHA*CHA];        // 67 MB
__device__ float  g_Ur[BANDS*CHA*RRANK];
__device__ float  g_V[(size_t)BANDS*CHA*CHA];                  // warm-start V
__device__ float  g_T[(size_t)BANDS*CHA*CHA];                  // matmul temp
__device__ float  g_losspart[2][ITEN][BANDS*PB_CTAS];
__device__ double g_dpart[1024];
__device__ float  g_rho0;

// packed f32x2 fused-multiply-add (sm_100+ PTX; ptxas never auto-fuses)
#define FMA2(acc,aa,bb) asm("fma.rn.f32x2 %0, %1, %2, %3;" : "=l"(acc) : "l"(aa), "l"(bb), "l"(acc))
#define PACK2(dst,lo,hi) asm("mov.b64 %0,{%1,%2};" : "=l"(dst) : "f"(lo), "f"(hi))
#define PACKD(dst,v)     asm("mov.b64 %0,{%1,%1};" : "=l"(dst) : "f"(v))
#define UNPK2(lo,hi,src) asm("mov.b64 {%0,%1}, %2;" : "=f"(lo), "=f"(hi) : "l"(src))

// ============================================================
// rho0 partials = 0.5*mean(W) step 1; also seeds V = I (fused so
// the ncu capture at launch index 3 lands on k_eigen)
// ============================================================
__global__ __launch_bounds__(NTHREADS) void k_wsum1(const float* __restrict__ W)
{
    __shared__ double rd[NTHREADS];
    if (blockIdx.x < BANDS) {
        for (int e = threadIdx.x; e < CHA * CHA; e += NTHREADS)
            g_V[(size_t)blockIdx.x * (CHA * CHA) + e] = ((e >> 6) == (e & 63)) ? 1.0f : 0.0f;
    }
    const size_t base = (size_t)blockIdx.x * 65536;
    double s = 0.0;
    for (int i = threadIdx.x; i < 65536; i += NTHREADS) s += (double)W[base + i];
    rd[threadIdx.x] = s;
    __syncthreads();
    for (int st = NTHREADS/2; st > 0; st >>= 1) {
        if (threadIdx.x < st) rd[threadIdx.x] += rd[threadIdx.x + st];
        __syncthreads();
    }
    if (threadIdx.x == 0) g_dpart[blockIdx.x] = rd[0];
}

__global__ __launch_bounds__(NTHREADS) void k_wsum2()
{
    __shared__ double rd[NTHREADS];
    double s = 0.0;
    for (int i = threadIdx.x; i < 1024; i += NTHREADS) s += g_dpart[i];
    rd[threadIdx.x] = s;
    __syncthreads();
    for (int st = NTHREADS/2; st > 0; st >>= 1) {
        if (threadIdx.x < st) rd[threadIdx.x] += rd[threadIdx.x + st];
        __syncthreads();
    }
    if (threadIdx.x == 0) g_rho0 = (float)(0.5 * rd[0] / 67108864.0);
}

// ============================================================
// 8x4-blocked gram over the smem tile (two 64-pixel groups)
//   gg = tid>>7; id = tid&127; tr = (id>>4)<<3; tc = (id&15)<<2
//   16 packed accumulators (32 regs) — half R9's pressure
// ============================================================
__device__ __forceinline__ void gram8x4(const float* __restrict__ tile,
                                        int gg, int tr, int tc,
                                        unsigned long long acc[16])
{
    const int p0 = gg * 64;
#pragma unroll 4
    for (int pp = p0; pp < p0 + 64; ++pp) {
        const float4 a0 = *(const float4*)&tile[pp * TSTR + tr];
        const float4 a1 = *(const float4*)&tile[pp * TSTR + tr + 4];
        const float4 bv = *(const float4*)&tile[pp * TSTR + tc];
        unsigned long long B0, B1, A;
        PACK2(B0, bv.x, bv.y); PACK2(B1, bv.z, bv.w);
        PACKD(A, a0.x); FMA2(acc[0],  A, B0); FMA2(acc[1],  A, B1);
        PACKD(A, a0.y); FMA2(acc[2],  A, B0); FMA2(acc[3],  A, B1);
        PACKD(A, a0.z); FMA2(acc[4],  A, B0); FMA2(acc[5],  A, B1);
        PACKD(A, a0.w); FMA2(acc[6],  A, B0); FMA2(acc[7],  A, B1);
        PACKD(A, a1.x); FMA2(acc[8],  A, B0); FMA2(acc[9],  A, B1);
        PACKD(A, a1.y); FMA2(acc[10], A, B0); FMA2(acc[11], A, B1);
        PACKD(A, a1.z); FMA2(acc[12], A, B0); FMA2(acc[13], A, B1);
        PACKD(A, a1.w); FMA2(acc[14], A, B0); FMA2(acc[15], A, B1);
    }
}

__device__ __forceinline__ void gram_store(unsigned long long acc[16],
                                           int b, int cta, int gg, int tr, int tc)
{
    const size_t gb = (((size_t)(b * PB_CTAS + cta)) * 2 + gg) * (CHA * CHA);
#pragma unroll
    for (int i = 0; i < 8; ++i) {
#pragma unroll
        for (int j = 0; j < 2; ++j) {
            float lo, hi;
            UNPK2(lo, hi, acc[i * 2 + j]);
            g_Gpart[gb + (size_t)(tr + i) * CHA + tc + j * 2    ] = lo;
            g_Gpart[gb + (size_t)(tr + i) * CHA + tc + j * 2 + 1] = hi;
        }
    }
}

// ============================================================
// Gram of initial L (= x)
// ============================================================
__global__ __launch_bounds__(NTHREADS) void k_gram0(const float* __restrict__ x)
{
    __shared__ __align__(16) float tile[TP * TSTR];
    const int tid = threadIdx.x;
    const int cta = blockIdx.x;
    const int b   = blockIdx.y;
    const int p   = tid & 127;
    const int cg  = tid >> 7;
    const int gg  = tid >> 7;
    const int id  = tid & 127;
    const int tr  = (id >> 4) << 3;
    const int tc  = (id & 15) << 2;

    unsigned long long acc[16];
    { float z = 0.0f;
#pragma unroll
      for (int i = 0; i < 16; ++i) PACKD(acc[i], z); }

    for (int s = 0; s < SUBT; ++s) {
        const int n = cta * PIX_PER_CTA + s * TP + p;
        const size_t cbase = (((size_t)b * CHA + cg * 32) << 14) + n;
        __syncthreads();
#pragma unroll
        for (int q = 0; q < 8; ++q) {
            const size_t i0 = cbase + ((size_t)(q * 4) << 14);
            float4 v;
            v.x = x[i0];
            v.y = x[i0 + (size_t)(1 << 14)];
            v.z = x[i0 + (size_t)(2 << 14)];
            v.w = x[i0 + (size_t)(3 << 14)];
            *(float4*)&tile[p * TSTR + cg * 32 + q * 4] = v;
        }
        __syncthreads();
        gram8x4(tile, gg, tr, tc, acc);
    }
    gram_store(acc, b, cta, gg, tr, tc);
}

// ============================================================
// Eigen kernel: reduce G partials, warm-start pre-rotation,
// parallel Jacobi, full-off-diagonal convergence, write Ur + V
// ============================================================
__device__ __forceinline__ int rrperm(int k, int r)
{
    return (k == 0) ? 0 : 1 + ((k - 1 + r) % 63);
}

__global__ __launch_bounds__(NTHREADS) void k_eigen(int t)
{
    __shared__ float As[64 * 65];
    __shared__ float Vs[64 * 65];
    __shared__ float cs_c[32], cs_s[32];
    __shared__ int   ppv[32], qqv[32];
    __shared__ float red[NTHREADS];
    __shared__ float soff, sdg;
    __shared__ int   sflag;
    __shared__ int   topi[RRANK];

    const int tid = threadIdx.x;
    const int b   = blockIdx.x;
    const int tr  = (tid >> 4) << 2;
    const int tc  = (tid & 15) << 2;

    // reduce partial Grams (fixed order, vectorized)
    {
        const size_t base = (size_t)b * NPART * (CHA * CHA) + (size_t)tid * 16;
        float4 s0 = make_float4(0,0,0,0), s1 = s0, s2 = s0, s3 = s0;
        for (int pp = 0; pp < NPART; ++pp) {
            const float4* gp = (const float4*)&g_Gpart[base + (size_t)pp * (CHA * CHA)];
            float4 v0 = gp[0], v1 = gp[1], v2 = gp[2], v3 = gp[3];
            s0.x += v0.x; s0.y += v0.y; s0.z += v0.z; s0.w += v0.w;
            s1.x += v1.x; s1.y += v1.y; s1.z += v1.z; s1.w += v1.w;
            s2.x += v2.x; s2.y += v2.y; s2.z += v2.z; s2.w += v2.w;
            s3.x += v3.x; s3.y += v3.y; s3.z += v3.z; s3.w += v3.w;
        }
        const int e0 = tid * 16;
        float vals[16] = {s0.x,s0.y,s0.z,s0.w, s1.x,s1.y,s1.z,s1.w,
                          s2.x,s2.y,s2.z,s2.w, s3.x,s3.y,s3.z,s3.w};
#pragma unroll
        for (int k = 0; k < 16; ++k) {
            int e = e0 + k;
            As[(e >> 6) * 65 + (e & 63)] = vals[k];
        }
    }
    // load previous V (identity at t=0)
    for (int e = tid; e < CHA * CHA; e += NTHREADS)
        Vs[(e >> 6) * 65 + (e & 63)] = g_V[(size_t)b * (CHA * CHA) + e];
    __syncthreads();

    // warm-start pre-rotation: A <- V^T A V  (temp via global scratch)
    if (t > 0) {
        float* gT = g_T + (size_t)b * (CHA * CHA);
        float tt[16];
#pragma unroll
        for (int i = 0; i < 16; ++i) tt[i] = 0.0f;
        for (int k = 0; k < 64; ++k) {
            float a0 = As[(tr  ) * 65 + k], a1 = As[(tr+1) * 65 + k];
            float a2 = As[(tr+2) * 65 + k], a3 = As[(tr+3) * 65 + k];
            float v0 = Vs[k * 65 + tc], v1 = Vs[k * 65 + tc + 1];
            float v2 = Vs[k * 65 + tc + 2], v3 = Vs[k * 65 + tc + 3];
            tt[0]  += a0*v0; tt[1]  += a0*v1; tt[2]  += a0*v2; tt[3]  += a0*v3;
            tt[4]  += a1*v0; tt[5]  += a1*v1; tt[6]  += a1*v2; tt[7]  += a1*v3;
            tt[8]  += a2*v0; tt[9]  += a2*v1; tt[10] += a2*v2; tt[11] += a2*v3;
            tt[12] += a3*v0; tt[13] += a3*v1; tt[14] += a3*v2; tt[15] += a3*v3;
        }
#pragma unroll
        for (int i = 0; i < 4; ++i)
#pragma unroll
            for (int j = 0; j < 4; ++j)
                gT[(tr + i) * 64 + tc + j] = tt[i * 4 + j];
        __syncthreads();
#pragma unroll
        for (int i = 0; i < 16; ++i) tt[i] = 0.0f;
        for (int k = 0; k < 64; ++k) {
            float a0 = Vs[k * 65 + tr], a1 = Vs[k * 65 + tr + 1];
            float a2 = Vs[k * 65 + tr + 2], a3 = Vs[k * 65 + tr + 3];
            float v0 = gT[k * 64 + tc], v1 = gT[k * 64 + tc + 1];
            float v2 = gT[k * 64 + tc + 2], v3 = gT[k * 64 + tc + 3];
            tt[0]  += a0*v0; tt[1]  += a0*v1; tt[2]  += a0*v2; tt[3]  += a0*v3;
            tt[4]  += a1*v0; tt[5]  += a1*v1; tt[6]  += a1*v2; tt[7]  += a1*v3;
            tt[8]  += a2*v0; tt[9]  += a2*v1; tt[10] += a2*v2; tt[11] += a2*v3;
            tt[12] += a3*v0; tt[13] += a3*v1; tt[14] += a3*v2; tt[15] += a3*v3;
        }
        __syncthreads();
#pragma unroll
        for (int i = 0; i < 4; ++i)
#pragma unroll
            for (int j = 0; j < 4; ++j)
                As[(tr + i) * 65 + tc + j] = tt[i * 4 + j];
        __syncthreads();
    }

    for (int sw = 0; sw < MAXSWEEP; ++sw) {
        // convergence check BEFORE the sweep (warm starts exit early)
        float off = 0.0f, dg = 0.0f;
        for (int e = tid; e < 4096; e += NTHREADS) {
            int rr = e >> 6, cc = e & 63;
            float v = As[rr * 65 + cc];
            if (rr == cc) dg += v * v; else off += v * v;
        }
        red[tid] = off; __syncthreads();
        for (int st = NTHREADS/2; st > 0; st >>= 1) {
            if (tid < st) red[tid] += red[tid + st];
            __syncthreads();
        }
        if (tid == 0) soff = red[0];
        __syncthreads();
        red[tid] = dg; __syncthreads();
        for (int st = NTHREADS/2; st > 0; st >>= 1) {
            if (tid < st) red[tid] += red[tid + st];
            __syncthreads();
        }
        if (tid == 0) { sdg = red[0]; sflag = (soff < 1e-11f * sdg) ? 1 : 0; }
        __syncthreads();
        if (sflag) break;

        for (int r = 0; r < 63; ++r) {
            if (tid < 32) {
                int a  = rrperm(tid, r);
                int b2 = rrperm(63 - tid, r);
                int p = a < b2 ? a : b2;
                int q = a < b2 ? b2 : a;
                ppv[tid] = p; qqv[tid] = q;
                float apq = As[p * 65 + q];
                float cc = 1.0f, ss = 0.0f;
                if (fabsf(apq) > 1e-30f) {
                    float tau = (As[q * 65 + q] - As[p * 65 + p]) / (2.0f * apq);
                    float tt  = 1.0f / (fabsf(tau) + sqrtf(1.0f + tau * tau));
                    if (tau < 0.0f) tt = -tt;
                    cc = 1.0f / sqrtf(1.0f + tt * tt);
                    ss = tt * cc;
                }
                cs_c[tid] = cc; cs_s[tid] = ss;
            }
            __syncthreads();
            // column updates on A and V  (B = A*J, V = V*J)
            for (int task = tid; task < 4096; task += NTHREADS) {
                int pi  = task >> 7;
                int rem = task & 127;
                int row = rem & 63;
                int p = ppv[pi], q = qqv[pi];
                float c = cs_c[pi], s = cs_s[pi];
                if (rem < 64) {
                    float ap = As[row * 65 + p], aq = As[row * 65 + q];
                    As[row * 65 + p] = c * ap - s * aq;
                    As[row * 65 + q] = s * ap + c * aq;
                } else {
                    float vp = Vs[row * 65 + p], vq = Vs[row * 65 + q];
                    Vs[row * 65 + p] = c * vp - s * vq;
                    Vs[row * 65 + q] = s * vp + c * vq;
                }
            }
            __syncthreads();
            // row updates on A  (A = J^T * B)
            for (int task = tid; task < 2048; task += NTHREADS) {
                int pi  = task >> 6;
                int col = task & 63;
                int p = ppv[pi], q = qqv[pi];
                float c = cs_c[pi], s = cs_s[pi];
                float ap = As[p * 65 + col], aq = As[q * 65 + col];
                As[p * 65 + col] = c * ap - s * aq;
                As[q * 65 + col] = s * ap + c * aq;
            }
            __syncthreads();
        }
    }

    // top-3 selection (descending)
    if (tid == 0) {
        int t0 = -1, t1 = -1, t2 = -1;
        for (int j = 0; j < RRANK; ++j) {
            float best = -3.4e38f; int bi = -1;
            for (int c = 0; c < 64; ++c) {
                if (c == t0 || c == t1 || c == t2) continue;
                float v = As[c * 65 + c];
                if (v > best) { best = v; bi = c; }
            }
            if (j == 0) t0 = bi; else if (j == 1) t1 = bi; else t2 = bi;
            topi[j] = bi;
        }
    }
    __syncthreads();
    // persist V for warm start, write Ur
    for (int e = tid; e < CHA * CHA; e += NTHREADS)
        g_V[(size_t)b * (CHA * CHA) + e] = Vs[(e >> 6) * 65 + (e & 63)];
    if (tid < CHA * RRANK) {
        int c = tid / RRANK, j = tid % RRANK;
        g_Ur[b * (CHA * RRANK) + tid] = Vs[c * 65 + topi[j]];
    }
}

// ============================================================
// Fused per-iteration pass (R6 dataflow, 8x4 gram):
//   stage L tile -> c = Ur^T L -> UV, losses,
//   L_{t+1} (gmem + tile) -> fused gram
// Final iter: write UV to out, skip L/gram.
// ============================================================
__global__ __launch_bounds__(NTHREADS) void k_iter(const float* __restrict__ x,
                                                   const float* __restrict__ W,
                                                   float* __restrict__ out,
                                                   int t, int final, int useX)
{
    __shared__ __align__(16) float tile[TP * TSTR];   // 34816 B
    __shared__ float ur[CHA * RRANK];
    __shared__ float pc[3 * NTHREADS];
    __shared__ float red[NTHREADS];

    const int tid = threadIdx.x;
    const int cta = blockIdx.x;
    const int b   = blockIdx.y;
    const int p   = tid & 127;
    const int cg  = tid >> 7;          // channel half: 0 or 1
    const int gg  = tid >> 7;          // gram pixel group 0..1
    const int id  = tid & 127;
    const int tr  = (id >> 4) << 3;
    const int tc  = (id & 15) << 2;

    if (tid < CHA * RRANK) ur[tid] = g_Ur[b * (CHA * RRANK) + tid];
    __syncthreads();

    const float rho = g_rho0 * powf(1.05f, (float)t);
    const float* __restrict__ Ls = useX ? x : (const float*)g_L;

    unsigned long long acc[16];
    { float z = 0.0f;
#pragma unroll
      for (int i = 0; i < 16; ++i) PACKD(acc[i], z); }
    float lF = 0.0f, lU = 0.0f;

    for (int s = 0; s < SUBT; ++s) {
        const int n = cta * PIX_PER_CTA + s * TP + p;
        const size_t cbase = (((size_t)b * CHA + cg * 32) << 14) + n;

        __syncthreads();   // prev subtile's gram readers must finish
        // ---- stage L tile ----
#pragma unroll
        for (int q = 0; q < 8; ++q) {
            const size_t i0 = cbase + ((size_t)(q * 4) << 14);
            float4 v;
            v.x = Ls[i0];
            v.y = Ls[i0 + (size_t)(1 << 14)];
            v.z = Ls[i0 + (size_t)(2 << 14)];
            v.w = Ls[i0 + (size_t)(3 << 14)];
            *(float4*)&tile[p * TSTR + cg * 32 + q * 4] = v;
        }
        __syncthreads();

        // ---- phase A: c partials from tile ----
        float a0 = 0.0f, a1 = 0.0f, a2 = 0.0f;
#pragma unroll
        for (int q = 0; q < 8; ++q) {
            const int c0 = cg * 32 + q * 4;
            float4 lv = *(const float4*)&tile[p * TSTR + c0];
            a0 += ur[(c0  )*3  ] * lv.x; a1 += ur[(c0  )*3+1] * lv.x; a2 += ur[(c0  )*3+2] * lv.x;
            a0 += ur[(c0+1)*3  ] * lv.y; a1 += ur[(c0+1)*3+1] * lv.y; a2 += ur[(c0+1)*3+2] * lv.y;
            a0 += ur[(c0+2)*3  ] * lv.z; a1 += ur[(c0+2)*3+1] * lv.z; a2 += ur[(c0+2)*3+2] * lv.z;
            a0 += ur[(c0+3)*3  ] * lv.w; a1 += ur[(c0+3)*3+1] * lv.w; a2 += ur[(c0+3)*3+2] * lv.w;
        }
        pc[tid] = a0; pc[NTHREADS + tid] = a1; pc[2 * NTHREADS + tid] = a2;
        __syncthreads();
        const float C0 = pc[p] + pc[128 + p];
        const float C1 = pc[NTHREADS + p] + pc[NTHREADS + 128 + p];
        const float C2 = pc[2*NTHREADS + p] + pc[2*NTHREADS + 128 + p];

        // ---- phase B: UV, losses, L_{t+1} (gmem + tile) ----
#pragma unroll
        for (int q = 0; q < 8; ++q) {
            const int c0 = cg * 32 + q * 4;
            const size_t i0 = cbase + ((size_t)(q * 4) << 14);
            float lnv[4];
#pragma unroll
            for (int j = 0; j < 4; ++j) {
                const int cc = c0 + j;
                const size_t idx = i0 + ((size_t)j << 14);
                float uv = ur[cc*3] * C0 + ur[cc*3+1] * C1 + ur[cc*3+2] * C2;
                float xv = x[idx];
                float wv = W[idx];
                float d  = uv - xv;
                lF += wv * d * d;
                lU += uv * uv;
                if (final) {
                    out[idx] = uv;
                } else {
                    float mu = rho / (wv + rho);
                    float ln = xv + mu * (uv - xv);
                    g_L[idx] = ln;
                    lnv[j]   = ln;
                }
            }
            if (!final)
                *(float4*)&tile[p * TSTR + c0] = *(float4*)lnv;
        }

        if (!final) {
            __syncthreads();
            gram8x4(tile, gg, tr, tc, acc);
        }
    }

    if (!final) gram_store(acc, b, cta, gg, tr, tc);

    // deterministic loss partials
    __syncthreads();
    red[tid] = lF; __syncthreads();
    for (int st = NTHREADS/2; st > 0; st >>= 1) {
        if (tid < st) red[tid] += red[tid + st];
        __syncthreads();
    }
    if (tid == 0) g_losspart[0][t][b * PB_CTAS + cta] = red[0];
    __syncthreads();
    red[tid] = lU; __syncthreads();
    for (int st = NTHREADS/2; st > 0; st >>= 1) {
        if (tid < st) red[tid] += red[tid + st];
        __syncthreads();
    }
    if (tid == 0) g_losspart[1][t][b * PB_CTAS + cta] = red[0];
}

// ============================================================
// final loss reduction -> out tail
// ============================================================
__global__ __launch_bounds__(NTHREADS) void k_loss_final(float* __restrict__ out)
{
    __shared__ double rd[NTHREADS];
    const int id   = blockIdx.x;       // 0..39
    const int type = id / ITEN;        // 0 = loss_F, 1 = loss
    const int t    = id % ITEN;
    double s = 0.0;
    for (int i = threadIdx.x; i < BANDS * PB_CTAS; i += NTHREADS)
        s += (double)g_losspart[type][t][i];
    rd[threadIdx.x] = s;
    __syncthreads();
    for (int st = NTHREADS/2; st > 0; st >>= 1) {
        if (threadIdx.x < st) rd[threadIdx.x] += rd[threadIdx.x + st];
        __syncthreads();
    }
    if (threadIdx.x == 0)
        out[(size_t)67108864 + (size_t)type * ITEN + t] = (float)(rd[0] / 67108864.0);
}

// ============================================================
extern "C" void kernel_launch(void* const* d_in, const int* in_sizes, int n_in,
                              void* d_out, int out_size)
{
    const float* x = (const float*)d_in[0];
    const float* W = (const float*)d_in[1];
    float* out = (float*)d_out;

    k_wsum1<<<1024, NTHREADS>>>(W);                     // launch 0 (incl. V=I)
    k_wsum2<<<1, NTHREADS>>>();                         // launch 1
    k_gram0<<<dim3(PB_CTAS, BANDS), NTHREADS>>>(x);     // launch 2

    for (int t = 0; t < ITEN; ++t) {
        k_eigen<<<BANDS, NTHREADS>>>(t);                // launch 3 <- ncu capture (t=0)
        k_iter<<<dim3(PB_CTAS, BANDS), NTHREADS>>>(
            x, W, out, t, (t == ITEN - 1) ? 1 : 0, (t == 0) ? 1 : 0);
    }
    k_loss_final<<<40, NTHREADS>>>(out);
}

// round 11
// speedup vs baseline: 1.6244x; 1.3822x over previous
#include <cuda_runtime.h>
#include <math.h>

#define BANDS 64
#define CHA   64
#define NPIX  16384
#define RRANK 3
#define ITEN  20

#define PB_CTAS 32          // CTAs per band
#define SUBT    4           // subtiles per CTA
#define TP      128         // pixels per subtile
#define PIX_PER_CTA (SUBT*TP)   // 512
#define NTHREADS 256
#define ETHREADS 512        // eigen kernel threads (latency hiding)
#define MAXSWEEP 10
#define TSTR 68             // tile row stride in floats (272B, 16B-aligned)
#define NPART PB_CTAS       // 32 gram partials per band (one per CTA)

// ---- device scratch (static module memory; no runtime allocation) ----
__device__ float  g_L[(size_t)BANDS*CHA*NPIX];                 // 256 MB
__device__ float  g_Gpart[(size_t)BANDS*NPART*CHA*CHA];        // 33.5 MB
__device__ float  g_Ur[BANDS*CHA*RRANK];
__device__ float  g_V[(size_t)BANDS*CHA*CHA];                  // warm-start V
__device__ float  g_T[(size_t)BANDS*CHA*CHA];                  // matmul temp
__device__ float  g_losspart[2][ITEN][BANDS*PB_CTAS];
__device__ double g_dpart[1024];
__device__ float  g_rho0;

// packed f32x2 fused-multiply-add (sm_100+ PTX; ptxas never auto-fuses)
#define FMA2(acc,aa,bb) asm("fma.rn.f32x2 %0, %1, %2, %3;" : "=l"(acc) : "l"(aa), "l"(bb), "l"(acc))
#define PACK2(dst,lo,hi) asm("mov.b64 %0,{%1,%2};" : "=l"(dst) : "f"(lo), "f"(hi))
#define PACKD(dst,v)     asm("mov.b64 %0,{%1,%1};" : "=l"(dst) : "f"(v))
#define UNPK2(lo,hi,src) asm("mov.b64 {%0,%1}, %2;" : "=f"(lo), "=f"(hi) : "l"(src))

// ============================================================
// rho0 partials = 0.5*mean(W) step 1; also seeds V = I
// ============================================================
__global__ __launch_bounds__(NTHREADS) void k_wsum1(const float* __restrict__ W)
{
    __shared__ double rd[NTHREADS];
    if (blockIdx.x < BANDS) {
        for (int e = threadIdx.x; e < CHA * CHA; e += NTHREADS)
            g_V[(size_t)blockIdx.x * (CHA * CHA) + e] = ((e >> 6) == (e & 63)) ? 1.0f : 0.0f;
    }
    const size_t base = (size_t)blockIdx.x * 65536;
    double s = 0.0;
    for (int i = threadIdx.x; i < 65536; i += NTHREADS) s += (double)W[base + i];
    rd[threadIdx.x] = s;
    __syncthreads();
    for (int st = NTHREADS/2; st > 0; st >>= 1) {
        if (threadIdx.x < st) rd[threadIdx.x] += rd[threadIdx.x + st];
        __syncthreads();
    }
    if (threadIdx.x == 0) g_dpart[blockIdx.x] = rd[0];
}

__global__ __launch_bounds__(NTHREADS) void k_wsum2()
{
    __shared__ double rd[NTHREADS];
    double s = 0.0;
    for (int i = threadIdx.x; i < 1024; i += NTHREADS) s += g_dpart[i];
    rd[threadIdx.x] = s;
    __syncthreads();
    for (int st = NTHREADS/2; st > 0; st >>= 1) {
        if (threadIdx.x < st) rd[threadIdx.x] += rd[threadIdx.x + st];
        __syncthreads();
    }
    if (threadIdx.x == 0) g_rho0 = (float)(0.5 * rd[0] / 67108864.0);
}

// ============================================================
// R6-proven 4x4 f32x2 gram: each of 256 threads covers a 4x4
// block over all 128 pixels of the tile. acc[8] = 16 regs.
// ============================================================
__device__ __forceinline__ void gram4x4(const float* __restrict__ tile,
                                        int tr, int tc,
                                        unsigned long long acc[8])
{
#pragma unroll 2
    for (int pp = 0; pp < TP; ++pp) {
        const float4 av = *(const float4*)&tile[pp * TSTR + tr];
        const float4 bv = *(const float4*)&tile[pp * TSTR + tc];
        unsigned long long B0, B1, A;
        PACK2(B0, bv.x, bv.y); PACK2(B1, bv.z, bv.w);
        PACKD(A, av.x); FMA2(acc[0], A, B0); FMA2(acc[1], A, B1);
        PACKD(A, av.y); FMA2(acc[2], A, B0); FMA2(acc[3], A, B1);
        PACKD(A, av.z); FMA2(acc[4], A, B0); FMA2(acc[5], A, B1);
        PACKD(A, av.w); FMA2(acc[6], A, B0); FMA2(acc[7], A, B1);
    }
}

__device__ __forceinline__ void gram_store(unsigned long long acc[8],
                                           int b, int cta, int tr, int tc)
{
    const size_t gb = ((size_t)(b * PB_CTAS + cta)) * (CHA * CHA);
#pragma unroll
    for (int i = 0; i < 4; ++i) {
        float lo, hi;
        UNPK2(lo, hi, acc[i * 2]);
        g_Gpart[gb + (size_t)(tr + i) * CHA + tc    ] = lo;
        g_Gpart[gb + (size_t)(tr + i) * CHA + tc + 1] = hi;
        UNPK2(lo, hi, acc[i * 2 + 1]);
        g_Gpart[gb + (size_t)(tr + i) * CHA + tc + 2] = lo;
        g_Gpart[gb + (size_t)(tr + i) * CHA + tc + 3] = hi;
    }
}

// ============================================================
// Gram of initial L (= x)
// ============================================================
__global__ __launch_bounds__(NTHREADS) void k_gram0(const float* __restrict__ x)
{
    __shared__ __align__(16) float tile[TP * TSTR];
    const int tid = threadIdx.x;
    const int cta = blockIdx.x;
    const int b   = blockIdx.y;
    const int p   = tid & 127;
    const int cg  = tid >> 7;
    const int tr  = (tid >> 4) << 2;
    const int tc  = (tid & 15) << 2;

    unsigned long long acc[8];
    { float z = 0.0f;
#pragma unroll
      for (int i = 0; i < 8; ++i) PACKD(acc[i], z); }

    for (int s = 0; s < SUBT; ++s) {
        const int n = cta * PIX_PER_CTA + s * TP + p;
        const size_t cbase = (((size_t)b * CHA + cg * 32) << 14) + n;
        __syncthreads();
#pragma unroll
        for (int q = 0; q < 8; ++q) {
            const size_t i0 = cbase + ((size_t)(q * 4) << 14);
            float4 v;
            v.x = x[i0];
            v.y = x[i0 + (size_t)(1 << 14)];
            v.z = x[i0 + (size_t)(2 << 14)];
            v.w = x[i0 + (size_t)(3 << 14)];
            *(float4*)&tile[p * TSTR + cg * 32 + q * 4] = v;
        }
        __syncthreads();
        gram4x4(tile, tr, tc, acc);
    }
    gram_store(acc, b, cta, tr, tc);
}

// ============================================================
// Eigen kernel (512 threads): reduce G partials, warm-start
// pre-rotation, parallel Jacobi, full-off-diag convergence.
// Same rotation sequence/order as 256-thr version -> identical results.
// ============================================================
__device__ __forceinline__ int rrperm(int k, int r)
{
    return (k == 0) ? 0 : 1 + ((k - 1 + r) % 63);
}

__global__ __launch_bounds__(ETHREADS) void k_eigen(int t)
{
    __shared__ float As[64 * 65];
    __shared__ float Vs[64 * 65];
    __shared__ float cs_c[32], cs_s[32];
    __shared__ int   ppv[32], qqv[32];
    __shared__ float red[ETHREADS];
    __shared__ float soff, sdg;
    __shared__ int   sflag;
    __shared__ int   topi[RRANK];

    const int tid = threadIdx.x;
    const int b   = blockIdx.x;

    // reduce partial Grams (fixed order, vectorized): 8 elems/thread
    {
        const size_t base = (size_t)b * NPART * (CHA * CHA) + (size_t)tid * 8;
        float4 s0 = make_float4(0,0,0,0), s1 = s0;
        for (int pp = 0; pp < NPART; ++pp) {
            const float4* gp = (const float4*)&g_Gpart[base + (size_t)pp * (CHA * CHA)];
            float4 v0 = gp[0], v1 = gp[1];
            s0.x += v0.x; s0.y += v0.y; s0.z += v0.z; s0.w += v0.w;
            s1.x += v1.x; s1.y += v1.y; s1.z += v1.z; s1.w += v1.w;
        }
        const int e0 = tid * 8;
        float vals[8] = {s0.x,s0.y,s0.z,s0.w, s1.x,s1.y,s1.z,s1.w};
#pragma unroll
        for (int k = 0; k < 8; ++k) {
            int e = e0 + k;
            As[(e >> 6) * 65 + (e & 63)] = vals[k];
        }
    }
    // load previous V (identity at t=0)
    for (int e = tid; e < CHA * CHA; e += ETHREADS)
        Vs[(e >> 6) * 65 + (e & 63)] = g_V[(size_t)b * (CHA * CHA) + e];
    __syncthreads();

    // warm-start pre-rotation: A <- V^T A V  (temp via global scratch)
    // 512 threads: each computes a 4x2 block
    if (t > 0) {
        float* gT = g_T + (size_t)b * (CHA * CHA);
        const int tr = (tid >> 5) << 2;   // 16 row blocks * 4
        const int tc = (tid & 31) << 1;   // 32 col blocks * 2
        float tt[8];
#pragma unroll
        for (int i = 0; i < 8; ++i) tt[i] = 0.0f;
        for (int k = 0; k < 64; ++k) {
            float a0 = As[(tr  ) * 65 + k], a1 = As[(tr+1) * 65 + k];
            float a2 = As[(tr+2) * 65 + k], a3 = As[(tr+3) * 65 + k];
            float v0 = Vs[k * 65 + tc], v1 = Vs[k * 65 + tc + 1];
            tt[0] += a0*v0; tt[1] += a0*v1;
            tt[2] += a1*v0; tt[3] += a1*v1;
            tt[4] += a2*v0; tt[5] += a2*v1;
            tt[6] += a3*v0; tt[7] += a3*v1;
        }
#pragma unroll
        for (int i = 0; i < 4; ++i) {
            gT[(tr + i) * 64 + tc    ] = tt[i * 2];
            gT[(tr + i) * 64 + tc + 1] = tt[i * 2 + 1];
        }
        __syncthreads();
#pragma unroll
        for (int i = 0; i < 8; ++i) tt[i] = 0.0f;
        for (int k = 0; k < 64; ++k) {
            float a0 = Vs[k * 65 + tr], a1 = Vs[k * 65 + tr + 1];
            float a2 = Vs[k * 65 + tr + 2], a3 = Vs[k * 65 + tr + 3];
            float v0 = gT[k * 64 + tc], v1 = gT[k * 64 + tc + 1];
            tt[0] += a0*v0; tt[1] += a0*v1;
            tt[2] += a1*v0; tt[3] += a1*v1;
            tt[4] += a2*v0; tt[5] += a2*v1;
            tt[6] += a3*v0; tt[7] += a3*v1;
        }
        __syncthreads();
#pragma unroll
        for (int i = 0; i < 4; ++i) {
            As[(tr + i) * 65 + tc    ] = tt[i * 2];
            As[(tr + i) * 65 + tc + 1] = tt[i * 2 + 1];
        }
        __syncthreads();
    }

    for (int sw = 0; sw < MAXSWEEP; ++sw) {
        // convergence check BEFORE the sweep (warm starts exit early)
        float off = 0.0f, dg = 0.0f;
        for (int e = tid; e < 4096; e += ETHREADS) {
            int rr = e >> 6, cc = e & 63;
            float v = As[rr * 65 + cc];
            if (rr == cc) dg += v * v; else off += v * v;
        }
        red[tid] = off; __syncthreads();
        for (int st = ETHREADS/2; st > 0; st >>= 1) {
            if (tid < st) red[tid] += red[tid + st];
            __syncthreads();
        }
        if (tid == 0) soff = red[0];
        __syncthreads();
        red[tid] = dg; __syncthreads();
        for (int st = ETHREADS/2; st > 0; st >>= 1) {
            if (tid < st) red[tid] += red[tid + st];
            __syncthreads();
        }
        if (tid == 0) { sdg = red[0]; sflag = (soff < 1e-11f * sdg) ? 1 : 0; }
        __syncthreads();
        if (sflag) break;

        for (int r = 0; r < 63; ++r) {
            if (tid < 32) {
                int a  = rrperm(tid, r);
                int b2 = rrperm(63 - tid, r);
                int p = a < b2 ? a : b2;
                int q = a < b2 ? b2 : a;
                ppv[tid] = p; qqv[tid] = q;
                float apq = As[p * 65 + q];
                float cc = 1.0f, ss = 0.0f;
                if (fabsf(apq) > 1e-30f) {
                    float tau = (As[q * 65 + q] - As[p * 65 + p]) / (2.0f * apq);
                    float tt  = 1.0f / (fabsf(tau) + sqrtf(1.0f + tau * tau));
                    if (tau < 0.0f) tt = -tt;
                    cc = 1.0f / sqrtf(1.0f + tt * tt);
                    ss = tt * cc;
                }
                cs_c[tid] = cc; cs_s[tid] = ss;
            }
            __syncthreads();
            // column updates on A and V  (B = A*J, V = V*J): 8 tasks/thread
            for (int task = tid; task < 4096; task += ETHREADS) {
                int pi  = task >> 7;
                int rem = task & 127;
                int row = rem & 63;
                int p = ppv[pi], q = qqv[pi];
                float c = cs_c[pi], s = cs_s[pi];
                if (rem < 64) {
                    float ap = As[row * 65 + p], aq = As[row * 65 + q];
                    As[row * 65 + p] = c * ap - s * aq;
                    As[row * 65 + q] = s * ap + c * aq;
                } else {
                    float vp = Vs[row * 65 + p], vq = Vs[row * 65 + q];
                    Vs[row * 65 + p] = c * vp - s * vq;
                    Vs[row * 65 + q] = s * vp + c * vq;
                }
            }
            __syncthreads();
            // row updates on A  (A = J^T * B): 4 tasks/thread
            for (int task = tid; task < 2048; task += ETHREADS) {
                int pi  = task >> 6;
                int col = task & 63;
                int p = ppv[pi], q = qqv[pi];
                float c = cs_c[pi], s = cs_s[pi];
                float ap = As[p * 65 + col], aq = As[q * 65 + col];
                As[p * 65 + col] = c * ap - s * aq;
                As[q * 65 + col] = s * ap + c * aq;
            }
            __syncthreads();
        }
    }

    // top-3 selection (descending)
    if (tid == 0) {
        int t0 = -1, t1 = -1, t2 = -1;
        for (int j = 0; j < RRANK; ++j) {
            float best = -3.4e38f; int bi = -1;
            for (int c = 0; c < 64; ++c) {
                if (c == t0 || c == t1 || c == t2) continue;
                float v = As[c * 65 + c];
                if (v > best) { best = v; bi = c; }
            }
            if (j == 0) t0 = bi; else if (j == 1) t1 = bi; else t2 = bi;
            topi[j] = bi;
        }
    }
    __syncthreads();
    // persist V for warm start, write Ur
    for (int e = tid; e < CHA * CHA; e += ETHREADS)
        g_V[(size_t)b * (CHA * CHA) + e] = Vs[(e >> 6) * 65 + (e & 63)];
    if (tid < CHA * RRANK) {
        int c = tid / RRANK, j = tid % RRANK;
        g_Ur[b * (CHA * RRANK) + tid] = Vs[c * 65 + topi[j]];
    }
}

// ============================================================
// Fused per-iteration pass (R6-proven dataflow + 4x4 gram):
//   stage L tile -> c = Ur^T L -> UV, losses,
//   L_{t+1} (gmem + tile) -> fused gram
// Final iter: write UV to out, skip L/gram.
// ============================================================
__global__ __launch_bounds__(NTHREADS) void k_iter(const float* __restrict__ x,
                                                   const float* __restrict__ W,
                                                   float* __restrict__ out,
                                                   int t, int final, int useX)
{
    __shared__ __align__(16) float tile[TP * TSTR];   // 34816 B
    __shared__ float ur[CHA * RRANK];
    __shared__ float pc[3 * NTHREADS];
    __shared__ float red[NTHREADS];

    const int tid = threadIdx.x;
    const int cta = blockIdx.x;
    const int b   = blockIdx.y;
    const int p   = tid & 127;
    const int cg  = tid >> 7;          // channel half: 0 or 1
    const int tr  = (tid >> 4) << 2;
    const int tc  = (tid & 15) << 2;

    if (tid < CHA * RRANK) ur[tid] = g_Ur[b * (CHA * RRANK) + tid];
    __syncthreads();

    const float rho = g_rho0 * powf(1.05f, (float)t);
    const float* __restrict__ Ls = useX ? x : (const float*)g_L;

    unsigned long long acc[8];
    { float z = 0.0f;
#pragma unroll
      for (int i = 0; i < 8; ++i) PACKD(acc[i], z); }
    float lF = 0.0f, lU = 0.0f;

    for (int s = 0; s < SUBT; ++s) {
        const int n = cta * PIX_PER_CTA + s * TP + p;
        const size_t cbase = (((size_t)b * CHA + cg * 32) << 14) + n;

        __syncthreads();   // prev subtile's gram readers must finish
        // ---- stage L tile ----
#pragma unroll
        for (int q = 0; q < 8; ++q) {
            const size_t i0 = cbase + ((size_t)(q * 4) << 14);
            float4 v;
            v.x = Ls[i0];
            v.y = Ls[i0 + (size_t)(1 << 14)];
            v.z = Ls[i0 + (size_t)(2 << 14)];
            v.w = Ls[i0 + (size_t)(3 << 14)];
            *(float4*)&tile[p * TSTR + cg * 32 + q * 4] = v;
        }
        __syncthreads();

        // ---- phase A: c partials from tile ----
        float a0 = 0.0f, a1 = 0.0f, a2 = 0.0f;
#pragma unroll
        for (int q = 0; q < 8; ++q) {
            const int c0 = cg * 32 + q * 4;
            float4 lv = *(const float4*)&tile[p * TSTR + c0];
            a0 += ur[(c0  )*3  ] * lv.x; a1 += ur[(c0  )*3+1] * lv.x; a2 += ur[(c0  )*3+2] * lv.x;
            a0 += ur[(c0+1)*3  ] * lv.y; a1 += ur[(c0+1)*3+1] * lv.y; a2 += ur[(c0+1)*3+2] * lv.y;
            a0 += ur[(c0+2)*3  ] * lv.z; a1 += ur[(c0+2)*3+1] * lv.z; a2 += ur[(c0+2)*3+2] * lv.z;
            a0 += ur[(c0+3)*3  ] * lv.w; a1 += ur[(c0+3)*3+1] * lv.w; a2 += ur[(c0+3)*3+2] * lv.w;
        }
        pc[tid] = a0; pc[NTHREADS + tid] = a1; pc[2 * NTHREADS + tid] = a2;
        __syncthreads();
        const float C0 = pc[p] + pc[128 + p];
        const float C1 = pc[NTHREADS + p] + pc[NTHREADS + 128 + p];
        const float C2 = pc[2*NTHREADS + p] + pc[2*NTHREADS + 128 + p];

        // ---- phase B: UV, losses, L_{t+1} (gmem + tile) ----
#pragma unroll
        for (int q = 0; q < 8; ++q) {
            const int c0 = cg * 32 + q * 4;
            const size_t i0 = cbase + ((size_t)(q * 4) << 14);
            float lnv[4];
#pragma unroll
            for (int j = 0; j < 4; ++j) {
                const int cc = c0 + j;
                const size_t idx = i0 + ((size_t)j << 14);
                float uv = ur[cc*3] * C0 + ur[cc*3+1] * C1 + ur[cc*3+2] * C2;
                float xv = x[idx];
                float wv = W[idx];
                float d  = uv - xv;
                lF += wv * d * d;
                lU += uv * uv;
                if (final) {
                    out[idx] = uv;
                } else {
                    float mu = rho / (wv + rho);
                    float ln = xv + mu * (uv - xv);
                    g_L[idx] = ln;
                    lnv[j]   = ln;
                }
            }
            if (!final)
                *(float4*)&tile[p * TSTR + c0] = *(float4*)lnv;
        }

        if (!final) {
            __syncthreads();
            gram4x4(tile, tr, tc, acc);
        }
    }

    if (!final) gram_store(acc, b, cta, tr, tc);

    // deterministic loss partials
    __syncthreads();
    red[tid] = lF; __syncthreads();
    for (int st = NTHREADS/2; st > 0; st >>= 1) {
        if (tid < st) red[tid] += red[tid + st];
        __syncthreads();
    }
    if (tid == 0) g_losspart[0][t][b * PB_CTAS + cta] = red[0];
    __syncthreads();
    red[tid] = lU; __syncthreads();
    for (int st = NTHREADS/2; st > 0; st >>= 1) {
        if (tid < st) red[tid] += red[tid + st];
        __syncthreads();
    }
    if (tid == 0) g_losspart[1][t][b * PB_CTAS + cta] = red[0];
}

// ============================================================
// final loss reduction -> out tail
// ============================================================
__global__ __launch_bounds__(NTHREADS) void k_loss_final(float* __restrict__ out)
{
    __shared__ double rd[NTHREADS];
    const int id   = blockIdx.x;       // 0..39
    const int type = id / ITEN;        // 0 = loss_F, 1 = loss
    const int t    = id % ITEN;
    double s = 0.0;
    for (int i = threadIdx.x; i < BANDS * PB_CTAS; i += NTHREADS)
        s += (double)g_losspart[type][t][i];
    rd[threadIdx.x] = s;
    __syncthreads();
    for (int st = NTHREADS/2; st > 0; st >>= 1) {
        if (threadIdx.x < st) rd[threadIdx.x] += rd[threadIdx.x + st];
        __syncthreads();
    }
    if (threadIdx.x == 0)
        out[(size_t)67108864 + (size_t)type * ITEN + t] = (float)(rd[0] / 67108864.0);
}

// ============================================================
extern "C" void kernel_launch(void* const* d_in, const int* in_sizes, int n_in,
                              void* d_out, int out_size)
{
    const float* x = (const float*)d_in[0];
    const float* W = (const float*)d_in[1];
    float* out = (float*)d_out;

    k_wsum1<<<1024, NTHREADS>>>(W);                     // launch 0 (incl. V=I)
    k_wsum2<<<1, NTHREADS>>>();                         // launch 1
    k_gram0<<<dim3(PB_CTAS, BANDS), NTHREADS>>>(x);     // launch 2

    for (int t = 0; t < ITEN; ++t) {
        k_eigen<<<BANDS, ETHREADS>>>(t);                // launch 3 <- ncu capture (t=0)
        k_iter<<<dim3(PB_CTAS, BANDS), NTHREADS>>>(
            x, W, out, t, (t == ITEN - 1) ? 1 : 0, (t == 0) ? 1 : 0);
    }
    k_loss_final<<<40, NTHREADS>>>(out);
}

// round 12
// speedup vs baseline: 1.7598x; 1.0833x over previous
#include <cuda_runtime.h>
#include <math.h>

#define BANDS 64
#define CHA   64
#define NPIX  16384
#define RRANK 3
#define ITEN  20

#define PB_CTAS 32          // CTAs per band
#define SUBT    4           // subtiles per CTA
#define TP      128         // pixels per subtile
#define PIX_PER_CTA (SUBT*TP)   // 512
#define NTHREADS 256
#define ETHREADS 512        // eigen kernel threads
#define MAXSWEEP 10
#define TSTR 68             // tile row stride in floats (272B, 16B-aligned)
#define ESTR 68             // eigen matrix column stride (16B-aligned columns)
#define NPART PB_CTAS       // 32 gram partials per band (one per CTA)

// ---- device scratch (static module memory; no runtime allocation) ----
__device__ float  g_L[(size_t)BANDS*CHA*NPIX];                 // 256 MB
__device__ float  g_Gpart[(size_t)BANDS*NPART*CHA*CHA];        // 33.5 MB
__device__ float  g_Ur[BANDS*CHA*RRANK];
__device__ float  g_V[(size_t)BANDS*CHA*CHA];                  // warm-start V (col-major c*64+r)
__device__ float  g_T[(size_t)BANDS*CHA*CHA];                  // matmul temp (row-major)
__device__ float  g_losspart[2][ITEN][BANDS*PB_CTAS];
__device__ double g_dpart[1024];
__device__ float  g_rho0;

// packed f32x2 fused-multiply-add (sm_100+ PTX; ptxas never auto-fuses)
#define FMA2(acc,aa,bb) asm("fma.rn.f32x2 %0, %1, %2, %3;" : "=l"(acc) : "l"(aa), "l"(bb), "l"(acc))
#define PACK2(dst,lo,hi) asm("mov.b64 %0,{%1,%2};" : "=l"(dst) : "f"(lo), "f"(hi))
#define PACKD(dst,v)     asm("mov.b64 %0,{%1,%1};" : "=l"(dst) : "f"(v))
#define UNPK2(lo,hi,src) asm("mov.b64 {%0,%1}, %2;" : "=f"(lo), "=f"(hi) : "l"(src))

// ============================================================
// rho0 partials = 0.5*mean(W) step 1; also seeds V = I
// ============================================================
__global__ __launch_bounds__(NTHREADS) void k_wsum1(const float* __restrict__ W)
{
    __shared__ double rd[NTHREADS];
    if (blockIdx.x < BANDS) {
        for (int e = threadIdx.x; e < CHA * CHA; e += NTHREADS)
            g_V[(size_t)blockIdx.x * (CHA * CHA) + e] = ((e >> 6) == (e & 63)) ? 1.0f : 0.0f;
    }
    const size_t base = (size_t)blockIdx.x * 65536;
    double s = 0.0;
    for (int i = threadIdx.x; i < 65536; i += NTHREADS) s += (double)W[base + i];
    rd[threadIdx.x] = s;
    __syncthreads();
    for (int st = NTHREADS/2; st > 0; st >>= 1) {
        if (threadIdx.x < st) rd[threadIdx.x] += rd[threadIdx.x + st];
        __syncthreads();
    }
    if (threadIdx.x == 0) g_dpart[blockIdx.x] = rd[0];
}

__global__ __launch_bounds__(NTHREADS) void k_wsum2()
{
    __shared__ double rd[NTHREADS];
    double s = 0.0;
    for (int i = threadIdx.x; i < 1024; i += NTHREADS) s += g_dpart[i];
    rd[threadIdx.x] = s;
    __syncthreads();
    for (int st = NTHREADS/2; st > 0; st >>= 1) {
        if (threadIdx.x < st) rd[threadIdx.x] += rd[threadIdx.x + st];
        __syncthreads();
    }
    if (threadIdx.x == 0) g_rho0 = (float)(0.5 * rd[0] / 67108864.0);
}

// ============================================================
// R6-proven 4x4 f32x2 gram (unchanged)
// ============================================================
__device__ __forceinline__ void gram4x4(const float* __restrict__ tile,
                                        int tr, int tc,
                                        unsigned long long acc[8])
{
#pragma unroll 2
    for (int pp = 0; pp < TP; ++pp) {
        const float4 av = *(const float4*)&tile[pp * TSTR + tr];
        const float4 bv = *(const float4*)&tile[pp * TSTR + tc];
        unsigned long long B0, B1, A;
        PACK2(B0, bv.x, bv.y); PACK2(B1, bv.z, bv.w);
        PACKD(A, av.x); FMA2(acc[0], A, B0); FMA2(acc[1], A, B1);
        PACKD(A, av.y); FMA2(acc[2], A, B0); FMA2(acc[3], A, B1);
        PACKD(A, av.z); FMA2(acc[4], A, B0); FMA2(acc[5], A, B1);
        PACKD(A, av.w); FMA2(acc[6], A, B0); FMA2(acc[7], A, B1);
    }
}

__device__ __forceinline__ void gram_store(unsigned long long acc[8],
                                           int b, int cta, int tr, int tc)
{
    const size_t gb = ((size_t)(b * PB_CTAS + cta)) * (CHA * CHA);
#pragma unroll
    for (int i = 0; i < 4; ++i) {
        float lo, hi;
        UNPK2(lo, hi, acc[i * 2]);
        g_Gpart[gb + (size_t)(tr + i) * CHA + tc    ] = lo;
        g_Gpart[gb + (size_t)(tr + i) * CHA + tc + 1] = hi;
        UNPK2(lo, hi, acc[i * 2 + 1]);
        g_Gpart[gb + (size_t)(tr + i) * CHA + tc + 2] = lo;
        g_Gpart[gb + (size_t)(tr + i) * CHA + tc + 3] = hi;
    }
}

// ============================================================
// Gram of initial L (= x)  (unchanged)
// ============================================================
__global__ __launch_bounds__(NTHREADS) void k_gram0(const float* __restrict__ x)
{
    __shared__ __align__(16) float tile[TP * TSTR];
    const int tid = threadIdx.x;
    const int cta = blockIdx.x;
    const int b   = blockIdx.y;
    const int p   = tid & 127;
    const int cg  = tid >> 7;
    const int tr  = (tid >> 4) << 2;
    const int tc  = (tid & 15) << 2;

    unsigned long long acc[8];
    { float z = 0.0f;
#pragma unroll
      for (int i = 0; i < 8; ++i) PACKD(acc[i], z); }

    for (int s = 0; s < SUBT; ++s) {
        const int n = cta * PIX_PER_CTA + s * TP + p;
        const size_t cbase = (((size_t)b * CHA + cg * 32) << 14) + n;
        __syncthreads();
#pragma unroll
        for (int q = 0; q < 8; ++q) {
            const size_t i0 = cbase + ((size_t)(q * 4) << 14);
            float4 v;
            v.x = x[i0];
            v.y = x[i0 + (size_t)(1 << 14)];
            v.z = x[i0 + (size_t)(2 << 14)];
            v.w = x[i0 + (size_t)(3 << 14)];
            *(float4*)&tile[p * TSTR + cg * 32 + q * 4] = v;
        }
        __syncthreads();
        gram4x4(tile, tr, tc, acc);
    }
    gram_store(acc, b, cta, tr, tc);
}

// ============================================================
// Eigen kernel (512 thr): col-major A/V, redundant per-pair
// rotation compute (no rotation barrier), float4 phase-1,
// 2 barriers/round, shuffle convergence check.
//   AS(r,c) = As[c*ESTR + r]  (A symmetric)
// ============================================================
__device__ __forceinline__ int rrperm(int k, int r)
{
    return (k == 0) ? 0 : 1 + ((k - 1 + r) % 63);
}

__global__ __launch_bounds__(ETHREADS) void k_eigen(int t)
{
    __shared__ __align__(16) float As[CHA * ESTR];   // 17408 B
    __shared__ __align__(16) float Vs[CHA * ESTR];   // 17408 B
    __shared__ float cs_c[32], cs_s[32];
    __shared__ int   ppv[32], qqv[32];
    __shared__ float redo[16], redd[16];
    __shared__ int   sflag;
    __shared__ int   topi[RRANK];

    const int tid  = threadIdx.x;
    const int b    = blockIdx.x;
    const int lane = tid & 31;
    const int wid  = tid >> 5;

    // reduce partial Grams (fixed order): 8 row-major elems/thread
    {
        const size_t base = (size_t)b * NPART * (CHA * CHA) + (size_t)tid * 8;
        float4 s0 = make_float4(0,0,0,0), s1 = s0;
        for (int pp = 0; pp < NPART; ++pp) {
            const float4* gp = (const float4*)&g_Gpart[base + (size_t)pp * (CHA * CHA)];
            float4 v0 = gp[0], v1 = gp[1];
            s0.x += v0.x; s0.y += v0.y; s0.z += v0.z; s0.w += v0.w;
            s1.x += v1.x; s1.y += v1.y; s1.z += v1.z; s1.w += v1.w;
        }
        const int e0 = tid * 8;
        float vals[8] = {s0.x,s0.y,s0.z,s0.w, s1.x,s1.y,s1.z,s1.w};
#pragma unroll
        for (int k = 0; k < 8; ++k) {
            int e = e0 + k;                     // row-major e = r*64 + c
            As[(e & 63) * ESTR + (e >> 6)] = vals[k];   // -> column-major
        }
    }
    // load previous V (col-major c*64+r in gmem)
    for (int e = tid; e < CHA * CHA; e += ETHREADS)
        Vs[(e >> 6) * ESTR + (e & 63)] = g_V[(size_t)b * (CHA * CHA) + e];
    __syncthreads();

    // warm-start pre-rotation: A <- V^T A V  (temp in g_T, row-major)
    if (t > 0) {
        float* gT = g_T + (size_t)b * (CHA * CHA);
        const int tr = (tid >> 5) << 2;   // 16 row blocks * 4
        const int tc = (tid & 31) << 1;   // 32 col blocks * 2
        float tt[8];
#pragma unroll
        for (int i = 0; i < 8; ++i) tt[i] = 0.0f;
        // T[r][c] = sum_k A[r][k] * V[k][c];  A[r][k] = As[k*ESTR + r]
        for (int k = 0; k < 64; ++k) {
            float4 av = *(const float4*)&As[k * ESTR + tr];   // rows tr..tr+3
            float v0 = Vs[tc * ESTR + k];
            float v1 = Vs[(tc + 1) * ESTR + k];
            tt[0] += av.x*v0; tt[1] += av.x*v1;
            tt[2] += av.y*v0; tt[3] += av.y*v1;
            tt[4] += av.z*v0; tt[5] += av.z*v1;
            tt[6] += av.w*v0; tt[7] += av.w*v1;
        }
#pragma unroll
        for (int i = 0; i < 4; ++i) {
            gT[(tr + i) * 64 + tc    ] = tt[i * 2];
            gT[(tr + i) * 64 + tc + 1] = tt[i * 2 + 1];
        }
        __syncthreads();
#pragma unroll
        for (int i = 0; i < 8; ++i) tt[i] = 0.0f;
        // A'[r][c] = sum_k V[k][r] * T[k][c];  V[k][r] = Vs[r*ESTR + k]
        for (int k = 0; k < 64; ++k) {
            float a0 = Vs[(tr    ) * ESTR + k], a1 = Vs[(tr + 1) * ESTR + k];
            float a2 = Vs[(tr + 2) * ESTR + k], a3 = Vs[(tr + 3) * ESTR + k];
            float t0 = gT[k * 64 + tc], t1 = gT[k * 64 + tc + 1];
            tt[0] += a0*t0; tt[1] += a0*t1;
            tt[2] += a1*t0; tt[3] += a1*t1;
            tt[4] += a2*t0; tt[5] += a2*t1;
            tt[6] += a3*t0; tt[7] += a3*t1;
        }
        __syncthreads();
#pragma unroll
        for (int i = 0; i < 4; ++i) {
            As[(tc    ) * ESTR + tr + i] = tt[i * 2];       // A'[tr+i][tc]
            As[(tc + 1) * ESTR + tr + i] = tt[i * 2 + 1];   // A'[tr+i][tc+1]
        }
        __syncthreads();
    }

    const int pi1   = tid >> 4;     // pair for phase 1 (16 threads each, half-warp)
    const int l16   = tid & 15;
    const int pi2   = tid & 31;     // pair for phase 2
    const int cgrp  = tid >> 5;     // 16 col groups of 4

    for (int sw = 0; sw < MAXSWEEP; ++sw) {
        // ---- convergence check (shuffle reduce, 2 barriers) ----
        float off = 0.0f, dg = 0.0f;
        for (int e = tid; e < 4096; e += ETHREADS) {
            int rr = e & 63, cc = e >> 6;
            float v = As[cc * ESTR + rr];
            if (rr == cc) dg += v * v; else off += v * v;
        }
#pragma unroll
        for (int o = 16; o > 0; o >>= 1) {
            off += __shfl_xor_sync(0xffffffffu, off, o);
            dg  += __shfl_xor_sync(0xffffffffu, dg,  o);
        }
        if (lane == 0) { redo[wid] = off; redd[wid] = dg; }
        __syncthreads();
        if (tid == 0) {
            float so = 0.0f, sd = 0.0f;
            for (int i = 0; i < 16; ++i) { so += redo[i]; sd += redd[i]; }
            sflag = (so < 1e-11f * sd) ? 1 : 0;
        }
        __syncthreads();
        if (sflag) break;

        for (int r = 0; r < 63; ++r) {
            // ---- rotation: redundant per-pair compute (warp-sync safe) ----
            int a  = rrperm(pi1, r);
            int b2 = rrperm(63 - pi1, r);
            int p = a < b2 ? a : b2;
            int q = a < b2 ? b2 : a;
            float app = As[p * ESTR + p];
            float aqq = As[q * ESTR + q];
            float apq = As[q * ESTR + p];
            float cc = 1.0f, ss = 0.0f;
            if (fabsf(apq) > 1e-30f) {
                float tau = (aqq - app) / (2.0f * apq);
                float tt  = 1.0f / (fabsf(tau) + sqrtf(1.0f + tau * tau));
                if (tau < 0.0f) tt = -tt;
                cc = 1.0f / sqrtf(1.0f + tt * tt);
                ss = tt * cc;
            }
            if (l16 == 0) { ppv[pi1] = p; qqv[pi1] = q; cs_c[pi1] = cc; cs_s[pi1] = ss; }

            // ---- phase 1: column rotations on A and V (float4) ----
            {
                float4* cpA = (float4*)&As[p * ESTR];
                float4* cqA = (float4*)&As[q * ESTR];
                float4 ap4 = cpA[l16], aq4 = cqA[l16];
                float4 np, nq;
                np.x = cc*ap4.x - ss*aq4.x;  nq.x = ss*ap4.x + cc*aq4.x;
                np.y = cc*ap4.y - ss*aq4.y;  nq.y = ss*ap4.y + cc*aq4.y;
                np.z = cc*ap4.z - ss*aq4.z;  nq.z = ss*ap4.z + cc*aq4.z;
                np.w = cc*ap4.w - ss*aq4.w;  nq.w = ss*ap4.w + cc*aq4.w;
                cpA[l16] = np; cqA[l16] = nq;

                float4* cpV = (float4*)&Vs[p * ESTR];
                float4* cqV = (float4*)&Vs[q * ESTR];
                float4 vp4 = cpV[l16], vq4 = cqV[l16];
                np.x = cc*vp4.x - ss*vq4.x;  nq.x = ss*vp4.x + cc*vq4.x;
                np.y = cc*vp4.y - ss*vq4.y;  nq.y = ss*vp4.y + cc*vq4.y;
                np.z = cc*vp4.z - ss*vq4.z;  nq.z = ss*vp4.z + cc*vq4.z;
                np.w = cc*vp4.w - ss*vq4.w;  nq.w = ss*vp4.w + cc*vq4.w;
                cpV[l16] = np; cqV[l16] = nq;
            }
            __syncthreads();

            // ---- phase 2: row rotations on A (lane <-> pair, 4 cols each) ----
            {
                int p2 = ppv[pi2], q2 = qqv[pi2];
                float c2 = cs_c[pi2], s2 = cs_s[pi2];
                int cb = cgrp * 4;
#pragma unroll
                for (int j = 0; j < 4; ++j) {
                    int base = (cb + j) * ESTR;
                    float ap = As[base + p2], aq = As[base + q2];
                    As[base + p2] = c2 * ap - s2 * aq;
                    As[base + q2] = s2 * ap + c2 * aq;
                }
            }
            __syncthreads();
        }
    }

    // top-3 selection (descending)
    if (tid == 0) {
        int t0 = -1, t1 = -1, t2 = -1;
        for (int j = 0; j < RRANK; ++j) {
            float best = -3.4e38f; int bi = -1;
            for (int c = 0; c < 64; ++c) {
                if (c == t0 || c == t1 || c == t2) continue;
                float v = As[c * ESTR + c];
                if (v > best) { best = v; bi = c; }
            }
            if (j == 0) t0 = bi; else if (j == 1) t1 = bi; else t2 = bi;
            topi[j] = bi;
        }
    }
    __syncthreads();
    // persist V (col-major), write Ur
    for (int e = tid; e < CHA * CHA; e += ETHREADS)
        g_V[(size_t)b * (CHA * CHA) + e] = Vs[(e >> 6) * ESTR + (e & 63)];
    if (tid < CHA * RRANK) {
        int c = tid / RRANK, j = tid % RRANK;
        g_Ur[b * (CHA * RRANK) + tid] = Vs[topi[j] * ESTR + c];
    }
}

// ============================================================
// Fused per-iteration pass (unchanged from R11)
// ============================================================
__global__ __launch_bounds__(NTHREADS) void k_iter(const float* __restrict__ x,
                                                   const float* __restrict__ W,
                                                   float* __restrict__ out,
                                                   int t, int final, int useX)
{
    __shared__ __align__(16) float tile[TP * TSTR];   // 34816 B
    __shared__ float ur[CHA * RRANK];
    __shared__ float pc[3 * NTHREADS];
    __shared__ float red[NTHREADS];

    const int tid = threadIdx.x;
    const int cta = blockIdx.x;
    const int b   = blockIdx.y;
    const int p   = tid & 127;
    const int cg  = tid >> 7;
    const int tr  = (tid >> 4) << 2;
    const int tc  = (tid & 15) << 2;

    if (tid < CHA * RRANK) ur[tid] = g_Ur[b * (CHA * RRANK) + tid];
    __syncthreads();

    const float rho = g_rho0 * powf(1.05f, (float)t);
    const float* __restrict__ Ls = useX ? x : (const float*)g_L;

    unsigned long long acc[8];
    { float z = 0.0f;
#pragma unroll
      for (int i = 0; i < 8; ++i) PACKD(acc[i], z); }
    float lF = 0.0f, lU = 0.0f;

    for (int s = 0; s < SUBT; ++s) {
        const int n = cta * PIX_PER_CTA + s * TP + p;
        const size_t cbase = (((size_t)b * CHA + cg * 32) << 14) + n;

        __syncthreads();
#pragma unroll
        for (int q = 0; q < 8; ++q) {
            const size_t i0 = cbase + ((size_t)(q * 4) << 14);
            float4 v;
            v.x = Ls[i0];
            v.y = Ls[i0 + (size_t)(1 << 14)];
            v.z = Ls[i0 + (size_t)(2 << 14)];
            v.w = Ls[i0 + (size_t)(3 << 14)];
            *(float4*)&tile[p * TSTR + cg * 32 + q * 4] = v;
        }
        __syncthreads();

        float a0 = 0.0f, a1 = 0.0f, a2 = 0.0f;
#pragma unroll
        for (int q = 0; q < 8; ++q) {
            const int c0 = cg * 32 + q * 4;
            float4 lv = *(const float4*)&tile[p * TSTR + c0];
            a0 += ur[(c0  )*3  ] * lv.x; a1 += ur[(c0  )*3+1] * lv.x; a2 += ur[(c0  )*3+2] * lv.x;
            a0 += ur[(c0+1)*3  ] * lv.y; a1 += ur[(c0+1)*3+1] * lv.y; a2 += ur[(c0+1)*3+2] * lv.y;
            a0 += ur[(c0+2)*3  ] * lv.z; a1 += ur[(c0+2)*3+1] * lv.z; a2 += ur[(c0+2)*3+2] * lv.z;
            a0 += ur[(c0+3)*3  ] * lv.w; a1 += ur[(c0+3)*3+1] * lv.w; a2 += ur[(c0+3)*3+2] * lv.w;
        }
        pc[tid] = a0; pc[NTHREADS + tid] = a1; pc[2 * NTHREADS + tid] = a2;
        __syncthreads();
        const float C0 = pc[p] + pc[128 + p];
        const float C1 = pc[NTHREADS + p] + pc[NTHREADS + 128 + p];
        const float C2 = pc[2*NTHREADS + p] + pc[2*NTHREADS + 128 + p];

#pragma unroll
        for (int q = 0; q < 8; ++q) {
            const int c0 = cg * 32 + q * 4;
            const size_t i0 = cbase + ((size_t)(q * 4) << 14);
            float lnv[4];
#pragma unroll
            for (int j = 0; j < 4; ++j) {
                const int cc = c0 + j;
                const size_t idx = i0 + ((size_t)j << 14);
                float uv = ur[cc*3] * C0 + ur[cc*3+1] * C1 + ur[cc*3+2] * C2;
                float xv = x[idx];
                float wv = W[idx];
                float d  = uv - xv;
                lF += wv * d * d;
                lU += uv * uv;
                if (final) {
                    out[idx] = uv;
                } else {
                    float mu = rho / (wv + rho);
                    float ln = xv + mu * (uv - xv);
                    g_L[idx] = ln;
                    lnv[j]   = ln;
                }
            }
            if (!final)
                *(float4*)&tile[p * TSTR + c0] = *(float4*)lnv;
        }

        if (!final) {
            __syncthreads();
            gram4x4(tile, tr, tc, acc);
        }
    }

    if (!final) gram_store(acc, b, cta, tr, tc);

    __syncthreads();
    red[tid] = lF; __syncthreads();
    for (int st = NTHREADS/2; st > 0; st >>= 1) {
        if (tid < st) red[tid] += red[tid + st];
        __syncthreads();
    }
    if (tid == 0) g_losspart[0][t][b * PB_CTAS + cta] = red[0];
    __syncthreads();
    red[tid] = lU; __syncthreads();
    for (int st = NTHREADS/2; st > 0; st >>= 1) {
        if (tid < st) red[tid] += red[tid + st];
        __syncthreads();
    }
    if (tid == 0) g_losspart[1][t][b * PB_CTAS + cta] = red[0];
}

// ============================================================
// final loss reduction -> out tail
// ============================================================
__global__ __launch_bounds__(NTHREADS) void k_loss_final(float* __restrict__ out)
{
    __shared__ double rd[NTHREADS];
    const int id   = blockIdx.x;       // 0..39
    const int type = id / ITEN;
    const int t    = id % ITEN;
    double s = 0.0;
    for (int i = threadIdx.x; i < BANDS * PB_CTAS; i += NTHREADS)
        s += (double)g_losspart[type][t][i];
    rd[threadIdx.x] = s;
    __syncthreads();
    for (int st = NTHREADS/2; st > 0; st >>= 1) {
        if (threadIdx.x < st) rd[threadIdx.x] += rd[threadIdx.x + st];
        __syncthreads();
    }
    if (threadIdx.x == 0)
        out[(size_t)67108864 + (size_t)type * ITEN + t] = (float)(rd[0] / 67108864.0);
}

// ============================================================
extern "C" void kernel_launch(void* const* d_in, const int* in_sizes, int n_in,
                              void* d_out, int out_size)
{
    const float* x = (const float*)d_in[0];
    const float* W = (const float*)d_in[1];
    float* out = (float*)d_out;

    k_wsum1<<<1024, NTHREADS>>>(W);                     // launch 0 (incl. V=I)
    k_wsum2<<<1, NTHREADS>>>();                         // launch 1
    k_gram0<<<dim3(PB_CTAS, BANDS), NTHREADS>>>(x);     // launch 2

    for (int t = 0; t < ITEN; ++t) {
        k_eigen<<<BANDS, ETHREADS>>>(t);                // launch 3 <- ncu capture (t=0)
        k_iter<<<dim3(PB_CTAS, BANDS), NTHREADS>>>(
            x, W, out, t, (t == ITEN - 1) ? 1 : 0, (t == 0) ? 1 : 0);
    }
    k_loss_final<<<40, NTHREADS>>>(out);
}